// round 1
// baseline (speedup 1.0000x reference)
#include <cuda_runtime.h>
#include <math.h>

// ---------------------------------------------------------------------------
// Aggregator: KG gather-scatter-mean + COO spmm + latent attention gating
// Output layout (float32): [entity_agg (100000*64) | user_agg (50000*64) | latent_new (8*64)]
// ---------------------------------------------------------------------------

#define N_ENT_MAX 100000

__device__ int   g_cnt[N_ENT_MAX];
__device__ float g_latent_lin[8 * 64];   // lin(latent_emb, W1, b1)
__device__ float g_latent_new[8 * 64];   // final latent_new

// ---------------------------------------------------------------------------
__global__ void zero_cnt_kernel(int n) {
    int i = blockIdx.x * blockDim.x + threadIdx.x;
    if (i < n) g_cnt[i] = 0;
}

// ---------------------------------------------------------------------------
// KG aggregate: neigh = entity_emb[tail] * weight[edge_type-1]; scatter-add by head.
// 16 threads per edge, one float4 per lane. Vector RED (no-return atomic).
__global__ void kg_edge_kernel(const float* __restrict__ ent,
                               const int*   __restrict__ eidx,
                               const int*   __restrict__ etype,
                               const float* __restrict__ wgt,
                               float*       __restrict__ sums,
                               int nE) {
    long long gid = (long long)blockIdx.x * blockDim.x + threadIdx.x;
    int e = (int)(gid >> 4);
    if (e >= nE) return;
    int sub  = (int)(gid & 15);
    int head = eidx[e];
    int tail = eidx[nE + e];
    int t    = etype[e] - 1;

    float4 v = *reinterpret_cast<const float4*>(ent + (size_t)tail * 64 + sub * 4);
    float4 w = *reinterpret_cast<const float4*>(wgt + (size_t)t    * 64 + sub * 4);
    float4 r;
    r.x = v.x * w.x; r.y = v.y * w.y; r.z = v.z * w.z; r.w = v.w * w.w;

    float* dst = sums + (size_t)head * 64 + sub * 4;
    asm volatile("red.global.add.v4.f32 [%0], {%1,%2,%3,%4};"
                 :: "l"(dst), "f"(r.x), "f"(r.y), "f"(r.z), "f"(r.w) : "memory");
    if (sub == 0) atomicAdd(&g_cnt[head], 1);
}

// ---------------------------------------------------------------------------
// user aggregate: interact_vals * entity_emb[cols], scatter-add by rows.
__global__ void interact_kernel(const float* __restrict__ ent,
                                const int*   __restrict__ rows,
                                const int*   __restrict__ cols,
                                const float* __restrict__ vals,
                                float*       __restrict__ uagg,
                                int nnz) {
    long long gid = (long long)blockIdx.x * blockDim.x + threadIdx.x;
    int e = (int)(gid >> 4);
    if (e >= nnz) return;
    int sub = (int)(gid & 15);
    int r   = rows[e];
    int c   = cols[e];
    float v = vals[e];

    float4 x = *reinterpret_cast<const float4*>(ent + (size_t)c * 64 + sub * 4);
    float4 out;
    out.x = v * x.x; out.y = v * x.y; out.z = v * x.z; out.w = v * x.w;

    float* dst = uagg + (size_t)r * 64 + sub * 4;
    asm volatile("red.global.add.v4.f32 [%0], {%1,%2,%3,%4};"
                 :: "l"(dst), "f"(out.x), "f"(out.y), "f"(out.z), "f"(out.w) : "memory");
}

// ---------------------------------------------------------------------------
// entity_agg = sums / max(cnt, 1)
__global__ void finalize_kernel(float* __restrict__ sums, int nEnt) {
    int gid = blockIdx.x * blockDim.x + threadIdx.x;
    if (gid >= nEnt * 16) return;
    int ent = gid >> 4;
    int c = g_cnt[ent];
    float inv = 1.0f / (float)(c > 1 ? c : 1);
    float4* p = reinterpret_cast<float4*>(sums) + gid;
    float4 v = *p;
    v.x *= inv; v.y *= inv; v.z *= inv; v.w *= inv;
    *p = v;
}

// ---------------------------------------------------------------------------
// Tiny latent chain (single block, 128 threads):
//   A = latent_emb @ W2^T + b2            [8,64]
//   B = weight     @ W2^T + b2            [16,64]
//   latent_lin = latent_emb @ W1^T + b1   [8,64]  (stashed for user kernel)
//   S = A @ B^T                            [8,16]
//   C = S @ W_wa^T + b_wa ; leaky(0.2)     [8,16]
//   D = softmax(C, axis=-1)
//   latent_new = D @ weight                [8,64]
__global__ void latent_kernel(const float* __restrict__ lat,
                              const float* __restrict__ wgt,
                              const float* __restrict__ W1, const float* __restrict__ b1,
                              const float* __restrict__ W2, const float* __restrict__ b2,
                              const float* __restrict__ Wwa, const float* __restrict__ bwa,
                              float* __restrict__ out_latent) {
    __shared__ float A[8][64];
    __shared__ float B[16][64];
    __shared__ float S[8][16];
    __shared__ float D[8][16];
    int tid = threadIdx.x;  // 128 threads

    for (int idx = tid; idx < 8 * 64; idx += 128) {
        int f = idx >> 6, j = idx & 63;
        float s = b2[j];
        for (int k = 0; k < 64; k++) s += lat[f * 64 + k] * W2[j * 64 + k];
        A[f][j] = s;
    }
    for (int idx = tid; idx < 16 * 64; idx += 128) {
        int r = idx >> 6, j = idx & 63;
        float s = b2[j];
        for (int k = 0; k < 64; k++) s += wgt[r * 64 + k] * W2[j * 64 + k];
        B[r][j] = s;
    }
    for (int idx = tid; idx < 8 * 64; idx += 128) {
        int f = idx >> 6, j = idx & 63;
        float s = b1[j];
        for (int k = 0; k < 64; k++) s += lat[f * 64 + k] * W1[j * 64 + k];
        g_latent_lin[idx] = s;
    }
    __syncthreads();

    {   // S: 8*16 = 128 outputs, one per thread
        int f = tid >> 4, r = tid & 15;
        float s = 0.0f;
        for (int j = 0; j < 64; j++) s += A[f][j] * B[r][j];
        S[f][r] = s;
    }
    __syncthreads();
    {   // C + leaky relu
        int f = tid >> 4, r = tid & 15;
        float s = bwa[r];
        for (int g = 0; g < 16; g++) s += S[f][g] * Wwa[r * 16 + g];
        D[f][r] = (s > 0.0f) ? s : 0.2f * s;
    }
    __syncthreads();
    if (tid < 8) {  // row softmax
        float m = -1e30f;
        for (int r = 0; r < 16; r++) m = fmaxf(m, D[tid][r]);
        float sum = 0.0f;
        for (int r = 0; r < 16; r++) { float e = expf(D[tid][r] - m); D[tid][r] = e; sum += e; }
        float inv = 1.0f / sum;
        for (int r = 0; r < 16; r++) D[tid][r] *= inv;
    }
    __syncthreads();
    for (int idx = tid; idx < 8 * 64; idx += 128) {
        int f = idx >> 6, c = idx & 63;
        float s = 0.0f;
        for (int r = 0; r < 16; r++) s += D[f][r] * wgt[r * 64 + c];
        g_latent_new[idx] = s;
        out_latent[idx]   = s;
    }
}

// ---------------------------------------------------------------------------
// Per-user gating: score = softmax(leaky(lin(u_lin @ latent_lin^T, Wua, bua)))
// user_agg *= (1 + score @ latent_new).   4 users per 256-thread block.
__global__ void user_kernel(const float* __restrict__ user_emb,
                            const float* __restrict__ W1, const float* __restrict__ b1,
                            const float* __restrict__ Wua, const float* __restrict__ bua,
                            float* __restrict__ uagg, int nUsers) {
    __shared__ float sW1t[64 * 65];   // transposed + padded (bank-conflict free)
    __shared__ float sLat[8 * 64];
    __shared__ float sLN[8 * 64];
    __shared__ float sU[4][64];
    __shared__ float sUL[4][64];
    __shared__ float sSc[4][8];
    __shared__ float sWua[64];
    __shared__ float sbua[8];
    __shared__ float sb1[64];

    int tid = threadIdx.x;  // 256

    for (int idx = tid; idx < 4096; idx += 256) {
        int j = idx >> 6, k = idx & 63;
        sW1t[k * 65 + j] = W1[idx];      // W1[j][k] -> sW1t[k][j]
    }
    for (int idx = tid; idx < 512; idx += 256) {
        sLat[idx] = g_latent_lin[idx];
        sLN[idx]  = g_latent_new[idx];
    }
    if (tid < 64) { sWua[tid] = Wua[tid]; sb1[tid] = b1[tid]; }
    if (tid < 8)  sbua[tid] = bua[tid];
    __syncthreads();

    int local = tid >> 6;        // user slot within block (0..3)
    int j     = tid & 63;        // channel
    int u     = blockIdx.x * 4 + local;
    bool active = (u < nUsers);

    float uval = active ? user_emb[(size_t)u * 64 + j] : 0.0f;
    sU[local][j] = uval;
    __syncthreads();

    // u_lin[j] = b1[j] + sum_k u[k] * W1[j][k]
    float s = sb1[j];
    #pragma unroll 8
    for (int k = 0; k < 64; k++) s += sU[local][k] * sW1t[k * 65 + j];
    sUL[local][j] = s;
    __syncthreads();

    // score_[f] = u_lin . latent_lin[f]
    if (j < 8) {
        float sc = 0.0f;
        for (int q = 0; q < 64; q++) sc += sUL[local][q] * sLat[j * 64 + q];
        sSc[local][j] = sc;
    }
    __syncthreads();

    // attention transform + leaky relu
    if (j < 8) {
        float t = sbua[j];
        #pragma unroll
        for (int g = 0; g < 8; g++) t += sSc[local][g] * sWua[j * 8 + g];
        sUL[local][j] = (t > 0.0f) ? t : 0.2f * t;
    }
    __syncthreads();

    // softmax over 8 factors
    if (j == 0) {
        float m = -1e30f;
        #pragma unroll
        for (int f = 0; f < 8; f++) m = fmaxf(m, sUL[local][f]);
        float e[8], sum = 0.0f;
        #pragma unroll
        for (int f = 0; f < 8; f++) { e[f] = expf(sUL[local][f] - m); sum += e[f]; }
        float inv = 1.0f / sum;
        #pragma unroll
        for (int f = 0; f < 8; f++) sSc[local][f] = e[f] * inv;
    }
    __syncthreads();

    if (active) {
        float m = 0.0f;
        #pragma unroll
        for (int f = 0; f < 8; f++) m += sSc[local][f] * sLN[f * 64 + j];
        size_t o = (size_t)u * 64 + j;
        float ua = uagg[o];
        uagg[o] = ua * m + ua;
    }
}

// ---------------------------------------------------------------------------
extern "C" void kernel_launch(void* const* d_in, const int* in_sizes, int n_in,
                              void* d_out, int out_size) {
    const float* ent   = (const float*)d_in[0];
    const float* usr   = (const float*)d_in[1];
    const float* lat   = (const float*)d_in[2];
    const int*   eidx  = (const int*)  d_in[3];
    const int*   etype = (const int*)  d_in[4];
    const int*   irow  = (const int*)  d_in[5];
    const int*   icol  = (const int*)  d_in[6];
    const float* ival  = (const float*)d_in[7];
    const float* wgt   = (const float*)d_in[8];
    // d_in[9] = entity_cate_set (unused by reference output)
    const float* Wua   = (const float*)d_in[10];
    const float* bua   = (const float*)d_in[11];
    const float* Wwa   = (const float*)d_in[12];
    const float* bwa   = (const float*)d_in[13];
    const float* W1    = (const float*)d_in[14];
    const float* b1    = (const float*)d_in[15];
    const float* W2    = (const float*)d_in[16];
    const float* b2    = (const float*)d_in[17];

    int nEnt = in_sizes[0] / 64;
    int nUsr = in_sizes[1] / 64;
    int nE   = in_sizes[4];
    int nnz  = in_sizes[5];

    float* out     = (float*)d_out;
    float* ent_agg = out;
    float* usr_agg = out + (size_t)nEnt * 64;
    float* lat_new = out + (size_t)nEnt * 64 + (size_t)nUsr * 64;

    // zero accumulators (output poisoned to 0xAA each timing run)
    cudaMemsetAsync(d_out, 0, (size_t)(nEnt + nUsr) * 64 * sizeof(float));
    zero_cnt_kernel<<<(nEnt + 255) / 256, 256>>>(nEnt);

    long long tE = (long long)nE * 16;
    kg_edge_kernel<<<(unsigned)((tE + 255) / 256), 256>>>(ent, eidx, etype, wgt, ent_agg, nE);

    long long tI = (long long)nnz * 16;
    interact_kernel<<<(unsigned)((tI + 255) / 256), 256>>>(ent, irow, icol, ival, usr_agg, nnz);

    finalize_kernel<<<(nEnt * 16 + 255) / 256, 256>>>(ent_agg, nEnt);

    latent_kernel<<<1, 128>>>(lat, wgt, W1, b1, W2, b2, Wwa, bwa, lat_new);

    user_kernel<<<(nUsr + 3) / 4, 256>>>(usr, W1, b1, Wua, bua, usr_agg, nUsr);
}

// round 2
// speedup vs baseline: 1.1189x; 1.1189x over previous
#include <cuda_runtime.h>
#include <math.h>

// ---------------------------------------------------------------------------
// Aggregator: CSR-ified KG gather-scatter-mean + COO spmm + latent attention.
// Strategy: counting sort edges by destination each launch (hist -> scan ->
// scatter), then one warp per destination accumulates in registers and writes
// the row ONCE (no float atomics at all).
// Output (float32): [entity_agg 100000*64 | user_agg 50000*64 | latent_new 8*64]
// ---------------------------------------------------------------------------

#define N_ENT 100000
#define N_USR 50000
#define N_EDG 2000000
#define N_NNZ 2000000
#define SCAN_CHUNK 1024
#define NBLK_E ((N_ENT + SCAN_CHUNK - 1) / SCAN_CHUNK)   // 98
#define NBLK_U ((N_USR + SCAN_CHUNK - 1) / SCAN_CHUNK)   // 49

__device__ int  g_cntE[N_ENT];
__device__ int  g_cntU[N_USR];
__device__ int  g_offE[N_ENT + 1];
__device__ int  g_offU[N_USR + 1];
__device__ int  g_curE[N_ENT];
__device__ int  g_curU[N_USR];
__device__ int  g_bsum[NBLK_E + NBLK_U];
__device__ int2 g_skg[N_EDG];   // {tail, type-1} sorted by head
__device__ int2 g_sit[N_NNZ];   // {col, bits(val)} sorted by row

__device__ float g_latent_lin[8 * 64];
__device__ float g_latent_new[8 * 64];

// ---------------------------------------------------------------------------
__global__ void zero_cnt_kernel(int nEnt, int nUsr) {
    int i = blockIdx.x * blockDim.x + threadIdx.x;
    if (i < nEnt) g_cntE[i] = 0;
    else { int j = i - nEnt; if (j < nUsr) g_cntU[j] = 0; }
}

// histogram both index streams in one kernel
__global__ void hist_kernel(const int* __restrict__ eidx,
                            const int* __restrict__ irow,
                            int nE, int nnz) {
    int i = blockIdx.x * blockDim.x + threadIdx.x;
    if (i < nE) atomicAdd(&g_cntE[eidx[i]], 1);
    else { int j = i - nE; if (j < nnz) atomicAdd(&g_cntU[irow[j]], 1); }
}

// scan phase 1: per-block reduce of counts
__global__ void scan_reduce_kernel(int nEnt, int nUsr) {
    __shared__ int s[256];
    int b = blockIdx.x, t = threadIdx.x;
    const int* src; int base, n;
    if (b < NBLK_E) { src = g_cntE; base = b * SCAN_CHUNK; n = nEnt; }
    else            { src = g_cntU; base = (b - NBLK_E) * SCAN_CHUNK; n = nUsr; }
    int sum = 0;
    for (int i = t; i < SCAN_CHUNK; i += 256) {
        int idx = base + i;
        if (idx < n) sum += src[idx];
    }
    s[t] = sum; __syncthreads();
    for (int d = 128; d > 0; d >>= 1) { if (t < d) s[t] += s[t + d]; __syncthreads(); }
    if (t == 0) g_bsum[b] = s[0];
}

// scan phase 2: scan the block sums (one block, 128 threads)
__global__ void scan_mid_kernel(int nEnt, int nUsr) {
    __shared__ int s[128];
    int t = threadIdx.x;
    // entity part
    int v = (t < NBLK_E) ? g_bsum[t] : 0;
    s[t] = v; __syncthreads();
    for (int d = 1; d < 128; d <<= 1) {
        int x = s[t]; if (t >= d) x += s[t - d];
        __syncthreads(); s[t] = x; __syncthreads();
    }
    if (t < NBLK_E) g_bsum[t] = s[t] - v;          // exclusive
    if (t == NBLK_E - 1) g_offE[nEnt] = s[t];      // total
    __syncthreads();
    // user part
    v = (t < NBLK_U) ? g_bsum[NBLK_E + t] : 0;
    s[t] = v; __syncthreads();
    for (int d = 1; d < 128; d <<= 1) {
        int x = s[t]; if (t >= d) x += s[t - d];
        __syncthreads(); s[t] = x; __syncthreads();
    }
    if (t < NBLK_U) g_bsum[NBLK_E + t] = s[t] - v;
    if (t == NBLK_U - 1) g_offU[nUsr] = s[t];
}

// scan phase 3: per-block exclusive scan + block prefix -> off / cur
__global__ void scan_final_kernel(int nEnt, int nUsr) {
    __shared__ int s[SCAN_CHUNK];
    int b = blockIdx.x, t = threadIdx.x;
    const int* cnt; int* off; int* cur; int base, n;
    if (b < NBLK_E) { cnt = g_cntE; off = g_offE; cur = g_curE; base = b * SCAN_CHUNK; n = nEnt; }
    else            { cnt = g_cntU; off = g_offU; cur = g_curU; base = (b - NBLK_E) * SCAN_CHUNK; n = nUsr; }
    int bpre = g_bsum[b];
    int idx = base + t;
    int v = (idx < n) ? cnt[idx] : 0;
    s[t] = v; __syncthreads();
    for (int d = 1; d < SCAN_CHUNK; d <<= 1) {
        int x = s[t]; if (t >= d) x += s[t - d];
        __syncthreads(); s[t] = x; __syncthreads();
    }
    int excl = s[t] - v + bpre;
    if (idx < n) { off[idx] = excl; cur[idx] = excl; }
}

// counting-sort scatter of both edge streams
__global__ void scatter_kernel(const int* __restrict__ eidx,
                               const int* __restrict__ etype,
                               const int* __restrict__ irow,
                               const int* __restrict__ icol,
                               const float* __restrict__ ival,
                               int nE, int nnz) {
    int i = blockIdx.x * blockDim.x + threadIdx.x;
    if (i < nE) {
        int head = eidx[i];
        int tail = eidx[nE + i];
        int ty   = etype[i] - 1;
        int pos = atomicAdd(&g_curE[head], 1);
        g_skg[pos] = make_int2(tail, ty);
    } else {
        int j = i - nE;
        if (j < nnz) {
            int r = irow[j];
            int pos = atomicAdd(&g_curU[r], 1);
            g_sit[pos] = make_int2(icol[j], __float_as_int(ival[j]));
        }
    }
}

// ---------------------------------------------------------------------------
// One warp per entity; lane owns channels [2*lane, 2*lane+1].
__global__ void kg_accum_kernel(const float* __restrict__ ent,
                                const float* __restrict__ wgt,
                                float* __restrict__ out, int nEnt) {
    __shared__ float swgt[16 * 64];
    int t = threadIdx.x;  // 256
    for (int i = t; i < 16 * 64; i += 256) swgt[i] = wgt[i];
    __syncthreads();

    int w = blockIdx.x * 8 + (t >> 5);
    int lane = t & 31;
    if (w >= nEnt) return;
    int start = g_offE[w], end = g_offE[w + 1];

    float2 acc = make_float2(0.f, 0.f);
    for (int base = start; base < end; base += 32) {
        int rem = end - base;
        int2 m = make_int2(0, 0);
        if (lane < rem) m = g_skg[base + lane];
        int lim = rem < 32 ? rem : 32;
        for (int j = 0; j < lim; j++) {
            int tail = __shfl_sync(0xffffffffu, m.x, j);
            int ty   = __shfl_sync(0xffffffffu, m.y, j);
            float2 e  = *reinterpret_cast<const float2*>(ent + (size_t)tail * 64 + lane * 2);
            float2 wv = *reinterpret_cast<const float2*>(swgt + ty * 64 + lane * 2);
            acc.x += e.x * wv.x;
            acc.y += e.y * wv.y;
        }
    }
    int cnt = end - start;
    float inv = 1.0f / (float)(cnt > 1 ? cnt : 1);
    float2 r = make_float2(acc.x * inv, acc.y * inv);
    *reinterpret_cast<float2*>(out + (size_t)w * 64 + lane * 2) = r;
}

// One warp per user.
__global__ void int_accum_kernel(const float* __restrict__ ent,
                                 float* __restrict__ uagg, int nUsr) {
    int t = threadIdx.x;
    int w = blockIdx.x * 8 + (t >> 5);
    int lane = t & 31;
    if (w >= nUsr) return;
    int start = g_offU[w], end = g_offU[w + 1];

    float2 acc = make_float2(0.f, 0.f);
    for (int base = start; base < end; base += 32) {
        int rem = end - base;
        int2 m = make_int2(0, 0);
        if (lane < rem) m = g_sit[base + lane];
        int lim = rem < 32 ? rem : 32;
        for (int j = 0; j < lim; j++) {
            int   col = __shfl_sync(0xffffffffu, m.x, j);
            float val = __int_as_float(__shfl_sync(0xffffffffu, m.y, j));
            float2 e = *reinterpret_cast<const float2*>(ent + (size_t)col * 64 + lane * 2);
            acc.x += val * e.x;
            acc.y += val * e.y;
        }
    }
    *reinterpret_cast<float2*>(uagg + (size_t)w * 64 + lane * 2) = acc;
}

// ---------------------------------------------------------------------------
// Tiny latent chain (single block, 128 threads).
__global__ void latent_kernel(const float* __restrict__ lat,
                              const float* __restrict__ wgt,
                              const float* __restrict__ W1, const float* __restrict__ b1,
                              const float* __restrict__ W2, const float* __restrict__ b2,
                              const float* __restrict__ Wwa, const float* __restrict__ bwa,
                              float* __restrict__ out_latent) {
    __shared__ float A[8][64];
    __shared__ float B[16][64];
    __shared__ float S[8][16];
    __shared__ float D[8][16];
    int tid = threadIdx.x;

    for (int idx = tid; idx < 8 * 64; idx += 128) {
        int f = idx >> 6, j = idx & 63;
        float s = b2[j];
        for (int k = 0; k < 64; k++) s += lat[f * 64 + k] * W2[j * 64 + k];
        A[f][j] = s;
    }
    for (int idx = tid; idx < 16 * 64; idx += 128) {
        int r = idx >> 6, j = idx & 63;
        float s = b2[j];
        for (int k = 0; k < 64; k++) s += wgt[r * 64 + k] * W2[j * 64 + k];
        B[r][j] = s;
    }
    for (int idx = tid; idx < 8 * 64; idx += 128) {
        int f = idx >> 6, j = idx & 63;
        float s = b1[j];
        for (int k = 0; k < 64; k++) s += lat[f * 64 + k] * W1[j * 64 + k];
        g_latent_lin[idx] = s;
    }
    __syncthreads();

    {
        int f = tid >> 4, r = tid & 15;
        float s = 0.0f;
        for (int j = 0; j < 64; j++) s += A[f][j] * B[r][j];
        S[f][r] = s;
    }
    __syncthreads();
    {
        int f = tid >> 4, r = tid & 15;
        float s = bwa[r];
        for (int g = 0; g < 16; g++) s += S[f][g] * Wwa[r * 16 + g];
        D[f][r] = (s > 0.0f) ? s : 0.2f * s;
    }
    __syncthreads();
    if (tid < 8) {
        float m = -1e30f;
        for (int r = 0; r < 16; r++) m = fmaxf(m, D[tid][r]);
        float sum = 0.0f;
        for (int r = 0; r < 16; r++) { float e = expf(D[tid][r] - m); D[tid][r] = e; sum += e; }
        float inv = 1.0f / sum;
        for (int r = 0; r < 16; r++) D[tid][r] *= inv;
    }
    __syncthreads();
    for (int idx = tid; idx < 8 * 64; idx += 128) {
        int f = idx >> 6, c = idx & 63;
        float s = 0.0f;
        for (int r = 0; r < 16; r++) s += D[f][r] * wgt[r * 64 + c];
        g_latent_new[idx] = s;
        out_latent[idx]   = s;
    }
}

// ---------------------------------------------------------------------------
// Per-user gating: user_agg *= (1 + score @ latent_new). 4 users / 256-thr block.
__global__ void user_kernel(const float* __restrict__ user_emb,
                            const float* __restrict__ W1, const float* __restrict__ b1,
                            const float* __restrict__ Wua, const float* __restrict__ bua,
                            float* __restrict__ uagg, int nUsers) {
    __shared__ float sW1t[64 * 65];
    __shared__ float sLat[8 * 64];
    __shared__ float sLN[8 * 64];
    __shared__ float sU[4][64];
    __shared__ float sUL[4][64];
    __shared__ float sSc[4][8];
    __shared__ float sWua[64];
    __shared__ float sbua[8];
    __shared__ float sb1[64];

    int tid = threadIdx.x;

    for (int idx = tid; idx < 4096; idx += 256) {
        int j = idx >> 6, k = idx & 63;
        sW1t[k * 65 + j] = W1[idx];
    }
    for (int idx = tid; idx < 512; idx += 256) {
        sLat[idx] = g_latent_lin[idx];
        sLN[idx]  = g_latent_new[idx];
    }
    if (tid < 64) { sWua[tid] = Wua[tid]; sb1[tid] = b1[tid]; }
    if (tid < 8)  sbua[tid] = bua[tid];
    __syncthreads();

    int local = tid >> 6;
    int j     = tid & 63;
    int u     = blockIdx.x * 4 + local;
    bool active = (u < nUsers);

    float uval = active ? user_emb[(size_t)u * 64 + j] : 0.0f;
    sU[local][j] = uval;
    __syncthreads();

    float s = sb1[j];
    #pragma unroll 8
    for (int k = 0; k < 64; k++) s += sU[local][k] * sW1t[k * 65 + j];
    sUL[local][j] = s;
    __syncthreads();

    if (j < 8) {
        float sc = 0.0f;
        for (int q = 0; q < 64; q++) sc += sUL[local][q] * sLat[j * 64 + q];
        sSc[local][j] = sc;
    }
    __syncthreads();

    if (j < 8) {
        float t = sbua[j];
        #pragma unroll
        for (int g = 0; g < 8; g++) t += sSc[local][g] * sWua[j * 8 + g];
        sUL[local][j] = (t > 0.0f) ? t : 0.2f * t;
    }
    __syncthreads();

    if (j == 0) {
        float m = -1e30f;
        #pragma unroll
        for (int f = 0; f < 8; f++) m = fmaxf(m, sUL[local][f]);
        float e[8], sum = 0.0f;
        #pragma unroll
        for (int f = 0; f < 8; f++) { e[f] = expf(sUL[local][f] - m); sum += e[f]; }
        float inv = 1.0f / sum;
        #pragma unroll
        for (int f = 0; f < 8; f++) sSc[local][f] = e[f] * inv;
    }
    __syncthreads();

    if (active) {
        float m = 0.0f;
        #pragma unroll
        for (int f = 0; f < 8; f++) m += sSc[local][f] * sLN[f * 64 + j];
        size_t o = (size_t)u * 64 + j;
        float ua = uagg[o];
        uagg[o] = ua * m + ua;
    }
}

// ---------------------------------------------------------------------------
extern "C" void kernel_launch(void* const* d_in, const int* in_sizes, int n_in,
                              void* d_out, int out_size) {
    const float* ent   = (const float*)d_in[0];
    const float* usr   = (const float*)d_in[1];
    const float* lat   = (const float*)d_in[2];
    const int*   eidx  = (const int*)  d_in[3];
    const int*   etype = (const int*)  d_in[4];
    const int*   irow  = (const int*)  d_in[5];
    const int*   icol  = (const int*)  d_in[6];
    const float* ival  = (const float*)d_in[7];
    const float* wgt   = (const float*)d_in[8];
    const float* Wua   = (const float*)d_in[10];
    const float* bua   = (const float*)d_in[11];
    const float* Wwa   = (const float*)d_in[12];
    const float* bwa   = (const float*)d_in[13];
    const float* W1    = (const float*)d_in[14];
    const float* b1    = (const float*)d_in[15];
    const float* W2    = (const float*)d_in[16];
    const float* b2    = (const float*)d_in[17];

    int nEnt = in_sizes[0] / 64;   // 100000
    int nUsr = in_sizes[1] / 64;   // 50000
    int nE   = in_sizes[4];        // 2000000
    int nnz  = in_sizes[5];        // 2000000

    float* out     = (float*)d_out;
    float* ent_agg = out;
    float* usr_agg = out + (size_t)nEnt * 64;
    float* lat_new = out + (size_t)nEnt * 64 + (size_t)nUsr * 64;

    // CSR build
    zero_cnt_kernel<<<(nEnt + nUsr + 255) / 256, 256>>>(nEnt, nUsr);
    hist_kernel<<<(nE + nnz + 255) / 256, 256>>>(eidx, irow, nE, nnz);
    scan_reduce_kernel<<<NBLK_E + NBLK_U, 256>>>(nEnt, nUsr);
    scan_mid_kernel<<<1, 128>>>(nEnt, nUsr);
    scan_final_kernel<<<NBLK_E + NBLK_U, SCAN_CHUNK>>>(nEnt, nUsr);
    scatter_kernel<<<(nE + nnz + 255) / 256, 256>>>(eidx, etype, irow, icol, ival, nE, nnz);

    // small dense chain (independent of CSR)
    latent_kernel<<<1, 128>>>(lat, wgt, W1, b1, W2, b2, Wwa, bwa, lat_new);

    // segment reductions (no atomics)
    kg_accum_kernel<<<(nEnt + 7) / 8, 256>>>(ent, wgt, ent_agg, nEnt);
    int_accum_kernel<<<(nUsr + 7) / 8, 256>>>(ent, usr_agg, nUsr);

    // per-user gating
    user_kernel<<<(nUsr + 3) / 4, 256>>>(usr, W1, b1, Wua, bua, usr_agg, nUsr);
}

// round 3
// speedup vs baseline: 1.3241x; 1.1834x over previous
#include <cuda_runtime.h>
#include <math.h>

// ---------------------------------------------------------------------------
// Aggregator: CSR counting-sort + fused register-resident segment reductions.
// Output (float32): [entity_agg 100000*64 | user_agg 50000*64 | latent_new 8*64]
// ---------------------------------------------------------------------------

#define N_ENT 100000
#define N_USR 50000
#define N_EDG 2000000
#define N_NNZ 2000000
#define SCAN_CHUNK 1024
#define NBLK_E ((N_ENT + SCAN_CHUNK - 1) / SCAN_CHUNK)   // 98
#define NBLK_U ((N_USR + SCAN_CHUNK - 1) / SCAN_CHUNK)   // 49

__device__ int  g_cntE[N_ENT];
__device__ int  g_cntU[N_USR];
__device__ int  g_offE[N_ENT + 1];
__device__ int  g_offU[N_USR + 1];
__device__ int  g_curE[N_ENT];
__device__ int  g_curU[N_USR];
__device__ int  g_bsum[NBLK_E + NBLK_U];
__device__ int  g_skgp[N_EDG];  // packed: tail | (type-1)<<17, sorted by head
__device__ int2 g_sit[N_NNZ];   // {col, bits(val)} sorted by row

__device__ float g_latent_lin[8 * 64];
__device__ float g_latent_new[8 * 64];

// smem layout for fused accum kernel (floats)
#define OFF_W1T 0              // 64 * 66 transposed+padded W1
#define OFF_LAT 4224           // 8 * 64
#define OFF_LN  4736           // 8 * 64
#define OFF_SU  5248           // 8 warps * 64
#define OFF_B1  5760           // 64
#define OFF_WUA 5824           // 64
#define OFF_BUA 5888           // 8
#define SMEM_FLOATS 5896

// ---------------------------------------------------------------------------
__global__ void zero_cnt_kernel(int nEnt, int nUsr) {
    int i = blockIdx.x * blockDim.x + threadIdx.x;
    if (i < nEnt) g_cntE[i] = 0;
    else { int j = i - nEnt; if (j < nUsr) g_cntU[j] = 0; }
}

__global__ void hist_kernel(const int* __restrict__ eidx,
                            const int* __restrict__ irow,
                            int nE, int nnz) {
    int i = blockIdx.x * blockDim.x + threadIdx.x;
    if (i < nE) atomicAdd(&g_cntE[eidx[i]], 1);
    else { int j = i - nE; if (j < nnz) atomicAdd(&g_cntU[irow[j]], 1); }
}

__global__ void scan_reduce_kernel(int nEnt, int nUsr) {
    __shared__ int s[256];
    int b = blockIdx.x, t = threadIdx.x;
    const int* src; int base, n;
    if (b < NBLK_E) { src = g_cntE; base = b * SCAN_CHUNK; n = nEnt; }
    else            { src = g_cntU; base = (b - NBLK_E) * SCAN_CHUNK; n = nUsr; }
    int sum = 0;
    for (int i = t; i < SCAN_CHUNK; i += 256) {
        int idx = base + i;
        if (idx < n) sum += src[idx];
    }
    s[t] = sum; __syncthreads();
    for (int d = 128; d > 0; d >>= 1) { if (t < d) s[t] += s[t + d]; __syncthreads(); }
    if (t == 0) g_bsum[b] = s[0];
}

__global__ void scan_mid_kernel(int nEnt, int nUsr) {
    __shared__ int s[128];
    int t = threadIdx.x;
    int v = (t < NBLK_E) ? g_bsum[t] : 0;
    s[t] = v; __syncthreads();
    for (int d = 1; d < 128; d <<= 1) {
        int x = s[t]; if (t >= d) x += s[t - d];
        __syncthreads(); s[t] = x; __syncthreads();
    }
    if (t < NBLK_E) g_bsum[t] = s[t] - v;
    if (t == NBLK_E - 1) g_offE[nEnt] = s[t];
    __syncthreads();
    v = (t < NBLK_U) ? g_bsum[NBLK_E + t] : 0;
    s[t] = v; __syncthreads();
    for (int d = 1; d < 128; d <<= 1) {
        int x = s[t]; if (t >= d) x += s[t - d];
        __syncthreads(); s[t] = x; __syncthreads();
    }
    if (t < NBLK_U) g_bsum[NBLK_E + t] = s[t] - v;
    if (t == NBLK_U - 1) g_offU[nUsr] = s[t];
}

__global__ void scan_final_kernel(int nEnt, int nUsr) {
    __shared__ int s[SCAN_CHUNK];
    int b = blockIdx.x, t = threadIdx.x;
    const int* cnt; int* off; int* cur; int base, n;
    if (b < NBLK_E) { cnt = g_cntE; off = g_offE; cur = g_curE; base = b * SCAN_CHUNK; n = nEnt; }
    else            { cnt = g_cntU; off = g_offU; cur = g_curU; base = (b - NBLK_E) * SCAN_CHUNK; n = nUsr; }
    int bpre = g_bsum[b];
    int idx = base + t;
    int v = (idx < n) ? cnt[idx] : 0;
    s[t] = v; __syncthreads();
    for (int d = 1; d < SCAN_CHUNK; d <<= 1) {
        int x = s[t]; if (t >= d) x += s[t - d];
        __syncthreads(); s[t] = x; __syncthreads();
    }
    int excl = s[t] - v + bpre;
    if (idx < n) { off[idx] = excl; cur[idx] = excl; }
}

__global__ void scatter_kernel(const int* __restrict__ eidx,
                               const int* __restrict__ etype,
                               const int* __restrict__ irow,
                               const int* __restrict__ icol,
                               const float* __restrict__ ival,
                               int nE, int nnz) {
    int i = blockIdx.x * blockDim.x + threadIdx.x;
    if (i < nE) {
        int head = eidx[i];
        int tail = eidx[nE + i];
        int ty   = etype[i] - 1;
        int pos = atomicAdd(&g_curE[head], 1);
        g_skgp[pos] = tail | (ty << 17);
    } else {
        int j = i - nE;
        if (j < nnz) {
            int r = irow[j];
            int pos = atomicAdd(&g_curU[r], 1);
            g_sit[pos] = make_int2(icol[j], __float_as_int(ival[j]));
        }
    }
}

// ---------------------------------------------------------------------------
// Tiny latent chain (single block, 128 threads).
__global__ void latent_kernel(const float* __restrict__ lat,
                              const float* __restrict__ wgt,
                              const float* __restrict__ W1, const float* __restrict__ b1,
                              const float* __restrict__ W2, const float* __restrict__ b2,
                              const float* __restrict__ Wwa, const float* __restrict__ bwa,
                              float* __restrict__ out_latent) {
    __shared__ float A[8][64];
    __shared__ float B[16][64];
    __shared__ float S[8][16];
    __shared__ float D[8][16];
    int tid = threadIdx.x;

    for (int idx = tid; idx < 8 * 64; idx += 128) {
        int f = idx >> 6, j = idx & 63;
        float s = b2[j];
        for (int k = 0; k < 64; k++) s += lat[f * 64 + k] * W2[j * 64 + k];
        A[f][j] = s;
    }
    for (int idx = tid; idx < 16 * 64; idx += 128) {
        int r = idx >> 6, j = idx & 63;
        float s = b2[j];
        for (int k = 0; k < 64; k++) s += wgt[r * 64 + k] * W2[j * 64 + k];
        B[r][j] = s;
    }
    for (int idx = tid; idx < 8 * 64; idx += 128) {
        int f = idx >> 6, j = idx & 63;
        float s = b1[j];
        for (int k = 0; k < 64; k++) s += lat[f * 64 + k] * W1[j * 64 + k];
        g_latent_lin[idx] = s;
    }
    __syncthreads();

    {
        int f = tid >> 4, r = tid & 15;
        float s = 0.0f;
        for (int j = 0; j < 64; j++) s += A[f][j] * B[r][j];
        S[f][r] = s;
    }
    __syncthreads();
    {
        int f = tid >> 4, r = tid & 15;
        float s = bwa[r];
        for (int g = 0; g < 16; g++) s += S[f][g] * Wwa[r * 16 + g];
        D[f][r] = (s > 0.0f) ? s : 0.2f * s;
    }
    __syncthreads();
    if (tid < 8) {
        float m = -1e30f;
        for (int r = 0; r < 16; r++) m = fmaxf(m, D[tid][r]);
        float sum = 0.0f;
        for (int r = 0; r < 16; r++) { float e = expf(D[tid][r] - m); D[tid][r] = e; sum += e; }
        float inv = 1.0f / sum;
        for (int r = 0; r < 16; r++) D[tid][r] *= inv;
    }
    __syncthreads();
    for (int idx = tid; idx < 8 * 64; idx += 128) {
        int f = idx >> 6, c = idx & 63;
        float s = 0.0f;
        for (int r = 0; r < 16; r++) s += D[f][r] * wgt[r * 64 + c];
        g_latent_new[idx] = s;
        out_latent[idx]   = s;
    }
}

// ---------------------------------------------------------------------------
// Fused segment reduction: entity blocks [0, EB), user blocks [EB, EB+UB).
// One warp per segment, lane owns channels 2*lane, 2*lane+1. MLP-4 inner loop.
// User path applies the attention gating inline (no extra pass over user_agg).
__global__ __launch_bounds__(256) void accum_kernel(
        const float* __restrict__ ent,
        const float* __restrict__ wgt,
        const float* __restrict__ usr,
        const float* __restrict__ W1,
        const float* __restrict__ b1,
        const float* __restrict__ Wua,
        const float* __restrict__ bua,
        float* __restrict__ ent_agg,
        float* __restrict__ usr_agg,
        int nEnt, int nUsr, int EB) {
    __shared__ float sbuf[SMEM_FLOATS];
    const unsigned FULL = 0xffffffffu;
    int t = threadIdx.x;
    int lane = t & 31;
    int wid = t >> 5;

    if (blockIdx.x < EB) {
        // ---------------- entity path ----------------
        for (int i = t; i < 1024; i += 256) sbuf[i] = wgt[i];
        __syncthreads();
        int w = blockIdx.x * 8 + wid;
        if (w >= nEnt) return;
        int start = g_offE[w], end = g_offE[w + 1];
        float2 acc = make_float2(0.f, 0.f);
        int base = start, n = end - start;
        while (n > 0) {
            int take = n < 32 ? n : 32;
            int m = (lane < take) ? g_skgp[base + lane] : 0;
            int j = 0;
            for (; j + 4 <= take; j += 4) {
                int a0 = __shfl_sync(FULL, m, j);
                int a1 = __shfl_sync(FULL, m, j + 1);
                int a2 = __shfl_sync(FULL, m, j + 2);
                int a3 = __shfl_sync(FULL, m, j + 3);
                float2 e0 = *reinterpret_cast<const float2*>(ent + (size_t)(a0 & 0x1FFFF) * 64 + lane * 2);
                float2 e1 = *reinterpret_cast<const float2*>(ent + (size_t)(a1 & 0x1FFFF) * 64 + lane * 2);
                float2 e2 = *reinterpret_cast<const float2*>(ent + (size_t)(a2 & 0x1FFFF) * 64 + lane * 2);
                float2 e3 = *reinterpret_cast<const float2*>(ent + (size_t)(a3 & 0x1FFFF) * 64 + lane * 2);
                float2 w0 = *reinterpret_cast<const float2*>(sbuf + (a0 >> 17) * 64 + lane * 2);
                float2 w1 = *reinterpret_cast<const float2*>(sbuf + (a1 >> 17) * 64 + lane * 2);
                float2 w2 = *reinterpret_cast<const float2*>(sbuf + (a2 >> 17) * 64 + lane * 2);
                float2 w3 = *reinterpret_cast<const float2*>(sbuf + (a3 >> 17) * 64 + lane * 2);
                acc.x += e0.x * w0.x; acc.y += e0.y * w0.y;
                acc.x += e1.x * w1.x; acc.y += e1.y * w1.y;
                acc.x += e2.x * w2.x; acc.y += e2.y * w2.y;
                acc.x += e3.x * w3.x; acc.y += e3.y * w3.y;
            }
            for (; j < take; j++) {
                int a = __shfl_sync(FULL, m, j);
                float2 e  = *reinterpret_cast<const float2*>(ent + (size_t)(a & 0x1FFFF) * 64 + lane * 2);
                float2 wv = *reinterpret_cast<const float2*>(sbuf + (a >> 17) * 64 + lane * 2);
                acc.x += e.x * wv.x; acc.y += e.y * wv.y;
            }
            base += take; n -= take;
        }
        int cnt = end - start;
        float inv = 1.0f / (float)(cnt > 1 ? cnt : 1);
        float2 r = make_float2(acc.x * inv, acc.y * inv);
        *reinterpret_cast<float2*>(ent_agg + (size_t)w * 64 + lane * 2) = r;
    } else {
        // ---------------- user path (accum + fused gating) ----------------
        for (int idx = t; idx < 4096; idx += 256) {
            int j = idx >> 6, k = idx & 63;
            sbuf[OFF_W1T + k * 66 + j] = W1[idx];
        }
        for (int idx = t; idx < 512; idx += 256) {
            sbuf[OFF_LAT + idx] = g_latent_lin[idx];
            sbuf[OFF_LN + idx]  = g_latent_new[idx];
        }
        if (t < 64) { sbuf[OFF_B1 + t] = b1[t]; sbuf[OFF_WUA + t] = Wua[t]; }
        if (t < 8)  sbuf[OFF_BUA + t] = bua[t];
        __syncthreads();

        int w = (blockIdx.x - EB) * 8 + wid;
        if (w >= nUsr) return;
        int start = g_offU[w], end = g_offU[w + 1];
        float2 acc = make_float2(0.f, 0.f);
        int base = start, n = end - start;
        while (n > 0) {
            int take = n < 32 ? n : 32;
            int2 m = (lane < take) ? g_sit[base + lane] : make_int2(0, 0);
            int j = 0;
            for (; j + 4 <= take; j += 4) {
                int c0 = __shfl_sync(FULL, m.x, j);
                int c1 = __shfl_sync(FULL, m.x, j + 1);
                int c2 = __shfl_sync(FULL, m.x, j + 2);
                int c3 = __shfl_sync(FULL, m.x, j + 3);
                float v0 = __int_as_float(__shfl_sync(FULL, m.y, j));
                float v1 = __int_as_float(__shfl_sync(FULL, m.y, j + 1));
                float v2 = __int_as_float(__shfl_sync(FULL, m.y, j + 2));
                float v3 = __int_as_float(__shfl_sync(FULL, m.y, j + 3));
                float2 e0 = *reinterpret_cast<const float2*>(ent + (size_t)c0 * 64 + lane * 2);
                float2 e1 = *reinterpret_cast<const float2*>(ent + (size_t)c1 * 64 + lane * 2);
                float2 e2 = *reinterpret_cast<const float2*>(ent + (size_t)c2 * 64 + lane * 2);
                float2 e3 = *reinterpret_cast<const float2*>(ent + (size_t)c3 * 64 + lane * 2);
                acc.x += v0 * e0.x; acc.y += v0 * e0.y;
                acc.x += v1 * e1.x; acc.y += v1 * e1.y;
                acc.x += v2 * e2.x; acc.y += v2 * e2.y;
                acc.x += v3 * e3.x; acc.y += v3 * e3.y;
            }
            for (; j < take; j++) {
                int   c = __shfl_sync(FULL, m.x, j);
                float v = __int_as_float(__shfl_sync(FULL, m.y, j));
                float2 e = *reinterpret_cast<const float2*>(ent + (size_t)c * 64 + lane * 2);
                acc.x += v * e.x; acc.y += v * e.y;
            }
            base += take; n -= take;
        }

        // gating: score = softmax(leaky(Wua @ (u_lin @ latent_lin^T) + bua))
        float2 uv = *reinterpret_cast<const float2*>(usr + (size_t)w * 64 + lane * 2);
        float* su = sbuf + OFF_SU + wid * 64;
        su[lane * 2] = uv.x; su[lane * 2 + 1] = uv.y;
        __syncwarp();

        float s0 = sbuf[OFF_B1 + 2 * lane], s1 = sbuf[OFF_B1 + 2 * lane + 1];
        #pragma unroll 8
        for (int k = 0; k < 64; k++) {
            float uk = su[k];
            float2 wv = *reinterpret_cast<const float2*>(sbuf + OFF_W1T + k * 66 + 2 * lane);
            s0 += uk * wv.x; s1 += uk * wv.y;
        }
        float sc[8];
        #pragma unroll
        for (int f = 0; f < 8; f++) {
            float2 lv = *reinterpret_cast<const float2*>(sbuf + OFF_LAT + f * 64 + lane * 2);
            sc[f] = s0 * lv.x + s1 * lv.y;
        }
        #pragma unroll
        for (int off = 16; off; off >>= 1) {
            #pragma unroll
            for (int f = 0; f < 8; f++) sc[f] += __shfl_xor_sync(FULL, sc[f], off);
        }
        float tv[8];
        #pragma unroll
        for (int f = 0; f < 8; f++) {
            float v = sbuf[OFF_BUA + f];
            #pragma unroll
            for (int g = 0; g < 8; g++) v += sc[g] * sbuf[OFF_WUA + f * 8 + g];
            tv[f] = (v > 0.f) ? v : 0.2f * v;
        }
        float mx = tv[0];
        #pragma unroll
        for (int f = 1; f < 8; f++) mx = fmaxf(mx, tv[f]);
        float ef[8], sum = 0.f;
        #pragma unroll
        for (int f = 0; f < 8; f++) { ef[f] = expf(tv[f] - mx); sum += ef[f]; }
        float sinv = 1.0f / sum;
        float2 g2 = make_float2(0.f, 0.f);
        #pragma unroll
        for (int f = 0; f < 8; f++) {
            float sf = ef[f] * sinv;
            float2 ln = *reinterpret_cast<const float2*>(sbuf + OFF_LN + f * 64 + lane * 2);
            g2.x += sf * ln.x; g2.y += sf * ln.y;
        }
        float2 r = make_float2(acc.x * (1.f + g2.x), acc.y * (1.f + g2.y));
        *reinterpret_cast<float2*>(usr_agg + (size_t)w * 64 + lane * 2) = r;
    }
}

// ---------------------------------------------------------------------------
extern "C" void kernel_launch(void* const* d_in, const int* in_sizes, int n_in,
                              void* d_out, int out_size) {
    const float* ent   = (const float*)d_in[0];
    const float* usr   = (const float*)d_in[1];
    const float* lat   = (const float*)d_in[2];
    const int*   eidx  = (const int*)  d_in[3];
    const int*   etype = (const int*)  d_in[4];
    const int*   irow  = (const int*)  d_in[5];
    const int*   icol  = (const int*)  d_in[6];
    const float* ival  = (const float*)d_in[7];
    const float* wgt   = (const float*)d_in[8];
    const float* Wua   = (const float*)d_in[10];
    const float* bua   = (const float*)d_in[11];
    const float* Wwa   = (const float*)d_in[12];
    const float* bwa   = (const float*)d_in[13];
    const float* W1    = (const float*)d_in[14];
    const float* b1    = (const float*)d_in[15];
    const float* W2    = (const float*)d_in[16];
    const float* b2    = (const float*)d_in[17];

    int nEnt = in_sizes[0] / 64;
    int nUsr = in_sizes[1] / 64;
    int nE   = in_sizes[4];
    int nnz  = in_sizes[5];

    float* out     = (float*)d_out;
    float* ent_agg = out;
    float* usr_agg = out + (size_t)nEnt * 64;
    float* lat_new = out + (size_t)nEnt * 64 + (size_t)nUsr * 64;

    // CSR build (counting sort by destination)
    zero_cnt_kernel<<<(nEnt + nUsr + 255) / 256, 256>>>(nEnt, nUsr);
    hist_kernel<<<(nE + nnz + 255) / 256, 256>>>(eidx, irow, nE, nnz);
    scan_reduce_kernel<<<NBLK_E + NBLK_U, 256>>>(nEnt, nUsr);
    scan_mid_kernel<<<1, 128>>>(nEnt, nUsr);
    scan_final_kernel<<<NBLK_E + NBLK_U, SCAN_CHUNK>>>(nEnt, nUsr);
    scatter_kernel<<<(nE + nnz + 255) / 256, 256>>>(eidx, etype, irow, icol, ival, nE, nnz);

    // small dense chain (produces g_latent_lin / g_latent_new / lat_new output)
    latent_kernel<<<1, 128>>>(lat, wgt, W1, b1, W2, b2, Wwa, bwa, lat_new);

    // fused segment reductions + user gating
    int EB = (nEnt + 7) / 8;
    int UB = (nUsr + 7) / 8;
    accum_kernel<<<EB + UB, 256>>>(ent, wgt, usr, W1, b1, Wua, bua,
                                   ent_agg, usr_agg, nEnt, nUsr, EB);
}